// round 4
// baseline (speedup 1.0000x reference)
#include <cuda_runtime.h>

// ---------------------------------------------------------------------------
// Quanvolution2D — closed-form Pauli-algebra evaluation (see R3 derivation).
//
//   <Z_i> = sum_T sign * prod_{q in T} sin(w1_q) * prod_{q in A_i\T} cos(w1_q)
//                 * prod_{j in M_T} sin(theta_j) * prod_{j in R_i\M_T} cos(theta_j)
//
// with theta = x + w0, masks derived constexpr from the CNOT ring permutation.
// Only 16 surviving monomials across the 4 filters.
//
// R4: one thread per (patch, channel) -> 3x shorter serial chains, full warps.
// Block = 96 (warp = channel, lane = patch-in-block). Channel mean via a tiny
// fixed-order shared-memory exchange: deterministic, no atomics.
// ---------------------------------------------------------------------------

namespace {

constexpr int NQ = 9;

// Forward basis permutation of one CNOT ring: CNOT(0,1), ..., CNOT(8,0)
__host__ __device__ constexpr int permP(int n) {
    int b[NQ] = {};
    for (int i = 0; i < NQ; ++i) b[i] = (n >> i) & 1;
    for (int i = 0; i < NQ; ++i) b[(i + 1) % NQ] ^= b[i];
    int r = 0;
    for (int i = 0; i < NQ; ++i) r |= b[i] << i;
    return r;
}
__host__ __device__ constexpr int invP(int y) {
    for (int n = 0; n < 512; ++n)
        if (permP(n) == y) return n;
    return 0;
}
// bit i of P(P(n)) == parity(n & rowPP(i))
__host__ __device__ constexpr int rowPP(int i) {
    int r = 0;
    for (int j = 0; j < NQ; ++j) {
        int y = permP(permP(1 << j));
        r |= ((y >> i) & 1) << j;
    }
    return r;
}
__host__ __device__ constexpr int cpop(int x) {
    int c = 0;
    while (x) { x &= x - 1; ++c; }
    return c;
}

constexpr int MAXT = 16;

struct TermTab {
    int   rmask[4];         // R_i: theta-support of filter i
    int   amask[4];         // A_i: w1 qubits entering filter i
    int   nt[4];            // surviving term count
    int   smask[4][MAXT];   // M_T: theta-sin mask (subset of R_i)
    int   tsub[4][MAXT];    // T:   w1-sin subset (subset of A_i)
    float sign[4][MAXT];
    bool  ok;
};

__host__ __device__ constexpr TermTab buildTerms() {
    TermTab T{};
    T.ok = true;
    int M[NQ] = {};
    for (int q = 0; q < NQ; ++q) M[q] = invP(1 << q);
    for (int i = 0; i < 4; ++i) {
        const int R = rowPP(i);
        T.rmask[i] = R;
        int A = 0;
        for (int q = 0; q < NQ; ++q)
            if (cpop(M[q] & R) & 1) A |= 1 << q;
        T.amask[i] = A;
        int n = 0;
        for (int s = 0; s < (1 << NQ); ++s) {
            if (s & ~A) continue;
            int xm = 0;
            for (int q = 0; q < NQ; ++q)
                if ((s >> q) & 1) xm ^= M[q];
            if (xm & ~R) continue;          // any X outside R -> <X>=0, dies
            const int e = cpop(s) + cpop(xm);
            if (e & 1) T.ok = false;        // surviving phase must be real
            if (n >= MAXT) { T.ok = false; continue; }
            T.smask[i][n] = xm;
            T.tsub[i][n]  = s;
            T.sign[i][n]  = ((e & 3) == 0) ? 1.f : -1.f;   // i^e = +/-1
            ++n;
        }
        T.nt[i] = n;
    }
    return T;
}

static_assert(buildTerms().ok, "Pauli term table invariant violated");
static_assert(buildTerms().nt[0] >= 1 && buildTerms().nt[1] >= 1 &&
              buildTerms().nt[2] >= 1 && buildTerms().nt[3] >= 1,
              "each filter must have at least the identity term");

__global__ void __launch_bounds__(96)
quanv_kernel(const float* __restrict__ x, const float* __restrict__ qw,
             float* __restrict__ out) {
    constexpr int C = 3, H = 28, W = 28, HO = 26, WO = 26;
    constexpr int NP = 4 * HO * WO;   // 2704 patches
    constexpr TermTab TT = buildTerms();

    const int lane = threadIdx.x & 31;   // patch within block
    const int ch   = threadIdx.x >> 5;   // warp -> channel
    const int patch = blockIdx.x * 32 + lane;
    const bool act = patch < NP;

    const int pc = act ? patch : 0;      // clamp for safe addressing
    const int xo = pc % WO;
    const int yo = (pc / WO) % HO;
    const int b  = pc / (WO * HO);

    // ---- Issue this thread's 9 input loads up front ----
    const float* xp = x + ((b * C + ch) * H + yo) * W + xo;
    float xv[NQ];
#pragma unroll
    for (int j = 0; j < NQ; ++j)
        xv[j] = __ldg(xp + (j / 3) * W + (j % 3));

    // ---- Uniform w0 / w1 trig (overlaps load latency; hits constant-cached L2)
    float w0[NQ], cw[NQ], sw[NQ];
#pragma unroll
    for (int q = 0; q < NQ; ++q) {
        w0[q] = __ldg(qw + q);
        __sincosf(__ldg(qw + NQ + q), &sw[q], &cw[q]);
    }

    // ---- Per-term coefficients from w1 (compile-time masks fold; CSE'd) ----
    float coef[4][MAXT];
#pragma unroll
    for (int i = 0; i < 4; ++i) {
#pragma unroll
        for (int t = 0; t < MAXT; ++t) {
            if (t < TT.nt[i]) {
                float p = TT.sign[i][t];
#pragma unroll
                for (int q = 0; q < NQ; ++q) {
                    if ((TT.amask[i] >> q) & 1)
                        p *= ((TT.tsub[i][t] >> q) & 1) ? sw[q] : cw[q];
                }
                coef[i][t] = p;
            }
        }
    }

    // ---- theta trig + 16 monomials ----
    float cth[NQ], sth[NQ];
#pragma unroll
    for (int j = 0; j < NQ; ++j)
        __sincosf(xv[j] + w0[j], &sth[j], &cth[j]);

    float z[4];
#pragma unroll
    for (int i = 0; i < 4; ++i) {
        float zi = 0.f;
#pragma unroll
        for (int t = 0; t < MAXT; ++t) {
            if (t < TT.nt[i]) {
                float p = coef[i][t];
#pragma unroll
                for (int j = 0; j < NQ; ++j) {
                    if ((TT.rmask[i] >> j) & 1)
                        p *= ((TT.smask[i][t] >> j) & 1) ? sth[j] : cth[j];
                }
                zi += p;
            }
        }
        z[i] = zi;
    }

    // ---- Fixed-order channel mean via shared memory (deterministic) ----
    __shared__ float red[2][32][4];      // channels 1,2 park results here
    if (ch != 0) {
#pragma unroll
        for (int f = 0; f < 4; ++f) red[ch - 1][lane][f] = z[f];
    }
    __syncthreads();

    if (ch == 0 && act) {
        const float inv3 = 1.f / 3.f;
#pragma unroll
        for (int f = 0; f < 4; ++f) {
            float v = (z[f] + red[0][lane][f] + red[1][lane][f]) * inv3;
            out[((b * 4 + f) * HO + yo) * WO + xo] = v;
        }
    }
}

}  // namespace

extern "C" void kernel_launch(void* const* d_in, const int* in_sizes, int n_in,
                              void* d_out, int out_size) {
    const float* x  = (const float*)d_in[0];   // (4,3,28,28) float32
    const float* qw = (const float*)d_in[1];   // (2,9) float32
    float* out = (float*)d_out;                // (4,4,26,26) float32

    // (2704 patches + 31) / 32 = 85 blocks of 96 threads (warp = channel).
    quanv_kernel<<<85, 96>>>(x, qw, out);
}

// round 5
// speedup vs baseline: 1.0435x; 1.0435x over previous
#include <cuda_runtime.h>

// ---------------------------------------------------------------------------
// Quanvolution2D — closed-form Pauli-algebra evaluation (derivation in R3).
//
//   <Z_i> = sum_T sign * prod_{q in T} sin(w1_q) * prod_{q in A_i\T} cos(w1_q)
//                 * prod_{j in M_T} sin(theta_j) * prod_{j in R_i\M_T} cos(theta_j)
//
// theta = x + w0; masks derived constexpr from the CNOT-ring GF(2) permutation;
// 16 surviving monomials across the 4 filters (compile-time verified).
//
// R5: channel-in-lane layout. lane = 3*patch_local + ch (patch_local 0..9,
// lanes 30/31 idle). The 3 channels of one patch are adjacent lanes, so the
// channel mean is two __shfl_down_sync (fixed summation order -> deterministic)
// instead of smem + __syncthreads. No smem, no barriers, no atomics.
// ---------------------------------------------------------------------------

namespace {

constexpr int NQ = 9;

// Forward basis permutation of one CNOT ring: CNOT(0,1), ..., CNOT(8,0)
__host__ __device__ constexpr int permP(int n) {
    int b[NQ] = {};
    for (int i = 0; i < NQ; ++i) b[i] = (n >> i) & 1;
    for (int i = 0; i < NQ; ++i) b[(i + 1) % NQ] ^= b[i];
    int r = 0;
    for (int i = 0; i < NQ; ++i) r |= b[i] << i;
    return r;
}
__host__ __device__ constexpr int invP(int y) {
    for (int n = 0; n < 512; ++n)
        if (permP(n) == y) return n;
    return 0;
}
// bit i of P(P(n)) == parity(n & rowPP(i))
__host__ __device__ constexpr int rowPP(int i) {
    int r = 0;
    for (int j = 0; j < NQ; ++j) {
        int y = permP(permP(1 << j));
        r |= ((y >> i) & 1) << j;
    }
    return r;
}
__host__ __device__ constexpr int cpop(int x) {
    int c = 0;
    while (x) { x &= x - 1; ++c; }
    return c;
}

constexpr int MAXT = 16;

struct TermTab {
    int   rmask[4];         // R_i: theta-support of filter i
    int   amask[4];         // A_i: w1 qubits entering filter i
    int   nt[4];            // surviving term count
    int   smask[4][MAXT];   // M_T: theta-sin mask (subset of R_i)
    int   tsub[4][MAXT];    // T:   w1-sin subset (subset of A_i)
    float sign[4][MAXT];
    bool  ok;
};

__host__ __device__ constexpr TermTab buildTerms() {
    TermTab T{};
    T.ok = true;
    int M[NQ] = {};
    for (int q = 0; q < NQ; ++q) M[q] = invP(1 << q);
    for (int i = 0; i < 4; ++i) {
        const int R = rowPP(i);
        T.rmask[i] = R;
        int A = 0;
        for (int q = 0; q < NQ; ++q)
            if (cpop(M[q] & R) & 1) A |= 1 << q;
        T.amask[i] = A;
        int n = 0;
        for (int s = 0; s < (1 << NQ); ++s) {
            if (s & ~A) continue;
            int xm = 0;
            for (int q = 0; q < NQ; ++q)
                if ((s >> q) & 1) xm ^= M[q];
            if (xm & ~R) continue;          // any X outside R -> <X>=0, dies
            const int e = cpop(s) + cpop(xm);
            if (e & 1) T.ok = false;        // surviving phase must be real
            if (n >= MAXT) { T.ok = false; continue; }
            T.smask[i][n] = xm;
            T.tsub[i][n]  = s;
            T.sign[i][n]  = ((e & 3) == 0) ? 1.f : -1.f;   // i^e = +/-1
            ++n;
        }
        T.nt[i] = n;
    }
    return T;
}

static_assert(buildTerms().ok, "Pauli term table invariant violated");
static_assert(buildTerms().nt[0] >= 1 && buildTerms().nt[1] >= 1 &&
              buildTerms().nt[2] >= 1 && buildTerms().nt[3] >= 1,
              "each filter must have at least the identity term");

constexpr unsigned FULL = 0xffffffffu;

__global__ void __launch_bounds__(96)
quanv_kernel(const float* __restrict__ x, const float* __restrict__ qw,
             float* __restrict__ out) {
    constexpr int C = 3, H = 28, W = 28, HO = 26, WO = 26;
    constexpr int NP = 4 * HO * WO;   // 2704 patches
    constexpr TermTab TT = buildTerms();

    const int lane = threadIdx.x & 31;
    const int wid  = threadIdx.x >> 5;
    const int ch   = lane % 3;            // channel of this lane
    const int pl   = lane / 3;            // patch slot within warp (0..9)
    const int patch = (blockIdx.x * 3 + wid) * 10 + pl;
    const bool act = (lane < 30) && (patch < NP);

    const int pc = act ? patch : 0;       // clamp for safe addressing
    const int xo = pc % WO;
    const int yo = (pc / WO) % HO;
    const int b  = pc / (WO * HO);

    // ---- Issue this thread's 9 input loads up front (MLP=9) ----
    const float* xp = x + ((b * C + ch) * H + yo) * W + xo;
    float xv[NQ];
#pragma unroll
    for (int j = 0; j < NQ; ++j)
        xv[j] = __ldg(xp + (j / 3) * W + (j % 3));

    // ---- Uniform w0 / w1 trig (overlaps x-load latency) ----
    float w0[NQ], cw[NQ], sw[NQ];
#pragma unroll
    for (int q = 0; q < NQ; ++q) {
        w0[q] = __ldg(qw + q);
        __sincosf(__ldg(qw + NQ + q), &sw[q], &cw[q]);
    }

    // ---- Per-term coefficients from w1 (compile-time masks fold; CSE'd) ----
    float coef[4][MAXT];
#pragma unroll
    for (int i = 0; i < 4; ++i) {
#pragma unroll
        for (int t = 0; t < MAXT; ++t) {
            if (t < TT.nt[i]) {
                float p = TT.sign[i][t];
#pragma unroll
                for (int q = 0; q < NQ; ++q) {
                    if ((TT.amask[i] >> q) & 1)
                        p *= ((TT.tsub[i][t] >> q) & 1) ? sw[q] : cw[q];
                }
                coef[i][t] = p;
            }
        }
    }

    // ---- theta trig (9 independent fast sincos) ----
    float cth[NQ], sth[NQ];
#pragma unroll
    for (int j = 0; j < NQ; ++j)
        __sincosf(xv[j] + w0[j], &sth[j], &cth[j]);

    // ---- 16 monomials across 4 filters ----
    float z[4];
#pragma unroll
    for (int i = 0; i < 4; ++i) {
        float zi = 0.f;
#pragma unroll
        for (int t = 0; t < MAXT; ++t) {
            if (t < TT.nt[i]) {
                float p = coef[i][t];
#pragma unroll
                for (int j = 0; j < NQ; ++j) {
                    if ((TT.rmask[i] >> j) & 1)
                        p *= ((TT.smask[i][t] >> j) & 1) ? sth[j] : cth[j];
                }
                zi += p;
            }
        }
        z[i] = zi;
    }

    // ---- Channel mean: the 3 channels of one patch are lanes 3p,3p+1,3p+2.
    // Capture both partner values first, then sum in fixed order (deterministic).
    const float inv3 = 1.f / 3.f;
#pragma unroll
    for (int f = 0; f < 4; ++f) {
        float z1 = __shfl_down_sync(FULL, z[f], 1);
        float z2 = __shfl_down_sync(FULL, z[f], 2);
        z[f] = (z[f] + z1 + z2) * inv3;
    }

    if (act && ch == 0) {
#pragma unroll
        for (int f = 0; f < 4; ++f)
            out[((b * 4 + f) * HO + yo) * WO + xo] = z[f];
    }
}

}  // namespace

extern "C" void kernel_launch(void* const* d_in, const int* in_sizes, int n_in,
                              void* d_out, int out_size) {
    const float* x  = (const float*)d_in[0];   // (4,3,28,28) float32
    const float* qw = (const float*)d_in[1];   // (2,9) float32
    float* out = (float*)d_out;                // (4,4,26,26) float32

    // 30 patches per 96-thread block (10 per warp): ceil(2704/30) = 91 blocks.
    quanv_kernel<<<91, 96>>>(x, qw, out);
}